// round 2
// baseline (speedup 1.0000x reference)
#include <cuda_runtime.h>
#include <cuda_bf16.h>

// MetaPolicyTransformer: N independent sequences, S=5, D=4, H=2 (hd=2), FF=16, L=3.
// 2 sequences per thread, packed into f32x2 (Blackwell packed fp32 math).

#define D_ 4
#define S_ 5
#define FF_ 16
#define L_ 3
#define BLK 128

typedef unsigned long long u64;

__device__ __forceinline__ u64 pk2(float lo, float hi) {
    u64 r; asm("mov.b64 %0, {%1, %2};" : "=l"(r) : "f"(lo), "f"(hi)); return r;
}
__device__ __forceinline__ void upk2(u64 v, float& lo, float& hi) {
    asm("mov.b64 {%0, %1}, %2;" : "=f"(lo), "=f"(hi) : "l"(v));
}
__device__ __forceinline__ u64 fma2(u64 a, u64 b, u64 c) {
    u64 r; asm("fma.rn.f32x2 %0, %1, %2, %3;" : "=l"(r) : "l"(a), "l"(b), "l"(c)); return r;
}
__device__ __forceinline__ u64 add2(u64 a, u64 b) {
    u64 r; asm("add.rn.f32x2 %0, %1, %2;" : "=l"(r) : "l"(a), "l"(b)); return r;
}
__device__ __forceinline__ u64 mul2(u64 a, u64 b) {
    u64 r; asm("mul.rn.f32x2 %0, %1, %2;" : "=l"(r) : "l"(a), "l"(b)); return r;
}
__device__ __forceinline__ float ex2a(float x) {
    float r; asm("ex2.approx.f32 %0, %1;" : "=f"(r) : "f"(x)); return r;
}
__device__ __forceinline__ float rcpa(float x) {
    float r; asm("rcp.approx.f32 %0, %1;" : "=f"(r) : "f"(x)); return r;
}
__device__ __forceinline__ u64 relu2(u64 v) {
    float a, b; upk2(v, a, b);
    return pk2(fmaxf(a, 0.0f), fmaxf(b, 0.0f));
}

__global__ __launch_bounds__(BLK, 2) void mpt_kernel(
    const float* __restrict__ xin,   // (N, 4, 4)
    const float* __restrict__ cls,   // (4,)
    const float* __restrict__ Wqkv,  // (3, 12, 4)
    const float* __restrict__ bqkv,  // (3, 12)
    const float* __restrict__ Wo,    // (3, 4, 4)
    const float* __restrict__ bo,    // (3, 4)
    const float* __restrict__ W1,    // (3, 16, 4)
    const float* __restrict__ b1,    // (3, 16)
    const float* __restrict__ W2,    // (3, 4, 16)
    const float* __restrict__ b2,    // (3, 4)
    float* __restrict__ out_fg,      // (N, 4)
    float* __restrict__ out_sub,     // (N, 16)
    int N)
{
    // all weights pre-packed {w, w} so LDS.64 feeds packed FMA directly
    __shared__ u64 sWqkv[L_ * 48];
    __shared__ u64 sbqkv[L_ * 12];
    __shared__ u64 sWo[L_ * 16];
    __shared__ u64 sbo[L_ * 4];
    __shared__ u64 sW1[L_ * 64];
    __shared__ u64 sb1[L_ * 16];
    __shared__ u64 sW2[L_ * 64];
    __shared__ u64 sb2[L_ * 4];
    __shared__ float scls[4];

    const int t = threadIdx.x;
    for (int i = t; i < L_ * 48; i += BLK) { float w = Wqkv[i]; sWqkv[i] = pk2(w, w); }
    for (int i = t; i < L_ * 12; i += BLK) { float w = bqkv[i]; sbqkv[i] = pk2(w, w); }
    for (int i = t; i < L_ * 16; i += BLK) { float w = Wo[i];   sWo[i]   = pk2(w, w); }
    for (int i = t; i < L_ * 4;  i += BLK) { float w = bo[i];   sbo[i]   = pk2(w, w); }
    for (int i = t; i < L_ * 64; i += BLK) { float w = W1[i];   sW1[i]   = pk2(w, w); }
    for (int i = t; i < L_ * 16; i += BLK) { float w = b1[i];   sb1[i]   = pk2(w, w); }
    for (int i = t; i < L_ * 64; i += BLK) { float w = W2[i];   sW2[i]   = pk2(w, w); }
    for (int i = t; i < L_ * 4;  i += BLK) { float w = b2[i];   sb2[i]   = pk2(w, w); }
    if (t < 4) scls[t] = cls[t];
    __syncthreads();

    const int n0 = blockIdx.x * (2 * BLK) + t;
    const int n1 = n0 + BLK;
    if (n0 >= N) return;
    const bool okB = (n1 < N);
    const int nB = okB ? n1 : n0;

    // PE: pe[s] = [sin(s), cos(s), sin(.01 s), cos(.01 s)]
    const float pe[S_][D_] = {
        { 0.0f,                  1.0f,                  0.0f,                   1.0f                 },
        { 0.84147098480789651f,  0.54030230586813977f,  0.0099998333341666645f, 0.99995000041666528f },
        { 0.90929742682568170f, -0.41614683654714241f,  0.019998666693333084f,  0.99980000666657776f },
        { 0.14112000805986722f, -0.98999249660044542f,  0.029995500337493652f,  0.99955003374899023f },
        { -0.75680249530792820f,-0.65364362086361194f,  0.039989334186634161f,  0.99920010665856564f }
    };

    u64 x[S_][D_];
    #pragma unroll
    for (int d = 0; d < D_; d++) {
        float c = scls[d] + pe[0][d];
        x[0][d] = pk2(c, c);
    }
    const float4* xa = reinterpret_cast<const float4*>(xin + (size_t)n0 * 16);
    const float4* xb = reinterpret_cast<const float4*>(xin + (size_t)nB * 16);
    #pragma unroll
    for (int s = 1; s < S_; s++) {
        float4 ra = xa[s - 1];
        float4 rb = xb[s - 1];
        x[s][0] = pk2(ra.x + pe[s][0], rb.x + pe[s][0]);
        x[s][1] = pk2(ra.y + pe[s][1], rb.y + pe[s][1]);
        x[s][2] = pk2(ra.z + pe[s][2], rb.z + pe[s][2]);
        x[s][3] = pk2(ra.w + pe[s][3], rb.w + pe[s][3]);
    }

    // 1/sqrt(2) * log2(e): softmax done in base-2 domain (identical function)
    const float SCL = 0.70710678118654752f * 1.4426950408889634f;
    const u64 SCL2 = pk2(SCL, SCL);

    #pragma unroll 1
    for (int l = 0; l < L_; l++) {
        const u64* wq  = sWqkv + l * 48;
        const u64* bq  = sbqkv + l * 12;
        const u64* wo  = sWo   + l * 16;
        const u64* bov = sbo   + l * 4;
        const u64* w1  = sW1   + l * 64;
        const u64* b1v = sb1   + l * 16;
        const u64* w2  = sW2   + l * 64;
        const u64* b2v = sb2   + l * 4;

        // V projection
        u64 v[S_][D_];
        #pragma unroll
        for (int s = 0; s < S_; s++) {
            #pragma unroll
            for (int o = 0; o < D_; o++) {
                u64 a = bq[8 + o];
                #pragma unroll
                for (int c = 0; c < D_; c++)
                    a = fma2(x[s][c], wq[(8 + o) * 4 + c], a);
                v[s][o] = a;
            }
        }

        u64 ao[S_][D_];
        #pragma unroll
        for (int h = 0; h < 2; h++) {
            // q (pre-scaled) and k for this head
            u64 qh[S_][2], kh[S_][2];
            #pragma unroll
            for (int s = 0; s < S_; s++) {
                #pragma unroll
                for (int e = 0; e < 2; e++) {
                    int o = 2 * h + e;
                    u64 aq = bq[o], ak = bq[4 + o];
                    #pragma unroll
                    for (int c = 0; c < D_; c++) {
                        aq = fma2(x[s][c], wq[o * 4 + c], aq);
                        ak = fma2(x[s][c], wq[(4 + o) * 4 + c], ak);
                    }
                    qh[s][e] = mul2(aq, SCL2);   // fold scale*log2e into q
                    kh[s][e] = ak;
                }
            }
            #pragma unroll
            for (int i = 0; i < S_; i++) {
                u64 sc[S_];
                #pragma unroll
                for (int j = 0; j < S_; j++) {
                    u64 s0 = mul2(qh[i][0], kh[j][0]);
                    sc[j] = fma2(qh[i][1], kh[j][1], s0);
                }
                // softmax in exp2 domain, unnormalized; scores are O(1), no max needed
                float eA[S_], eB[S_];
                float sA = 0.0f, sB = 0.0f;
                #pragma unroll
                for (int j = 0; j < S_; j++) {
                    float a, b; upk2(sc[j], a, b);
                    eA[j] = ex2a(a); eB[j] = ex2a(b);
                    sA += eA[j]; sB += eB[j];
                }
                u64 inv = pk2(rcpa(sA), rcpa(sB));
                u64 o0 = 0ull, o1 = 0ull;
                #pragma unroll
                for (int j = 0; j < S_; j++) {
                    u64 a = pk2(eA[j], eB[j]);
                    o0 = fma2(a, v[j][2 * h], o0);
                    o1 = fma2(a, v[j][2 * h + 1], o1);
                }
                ao[i][2 * h]     = mul2(o0, inv);
                ao[i][2 * h + 1] = mul2(o1, inv);
            }
        }

        // out-proj + residual
        #pragma unroll
        for (int s = 0; s < S_; s++) {
            u64 nx[D_];
            #pragma unroll
            for (int d = 0; d < D_; d++) {
                u64 a = bov[d];
                #pragma unroll
                for (int c = 0; c < D_; c++)
                    a = fma2(ao[s][c], wo[d * 4 + c], a);
                nx[d] = add2(x[s][d], a);
            }
            #pragma unroll
            for (int d = 0; d < D_; d++) x[s][d] = nx[d];
        }

        // FF + residual
        #pragma unroll
        for (int s = 0; s < S_; s++) {
            u64 h1[FF_];
            #pragma unroll
            for (int f = 0; f < FF_; f++) {
                u64 a = b1v[f];
                #pragma unroll
                for (int c = 0; c < D_; c++)
                    a = fma2(x[s][c], w1[f * 4 + c], a);
                h1[f] = relu2(a);
            }
            #pragma unroll
            for (int d = 0; d < D_; d++) {
                u64 a = b2v[d];
                #pragma unroll
                for (int f = 0; f < FF_; f++)
                    a = fma2(h1[f], w2[d * 16 + f], a);
                x[s][d] = add2(x[s][d], a);
            }
        }
    }

    // unpack + store
    float lo[S_][D_], hi[S_][D_];
    #pragma unroll
    for (int s = 0; s < S_; s++)
        #pragma unroll
        for (int d = 0; d < D_; d++)
            upk2(x[s][d], lo[s][d], hi[s][d]);

    reinterpret_cast<float4*>(out_fg + (size_t)n0 * 4)[0] =
        make_float4(lo[0][0], lo[0][1], lo[0][2], lo[0][3]);
    float4* subA = reinterpret_cast<float4*>(out_sub + (size_t)n0 * 16);
    #pragma unroll
    for (int s = 1; s < S_; s++)
        subA[s - 1] = make_float4(lo[s][0], lo[s][1], lo[s][2], lo[s][3]);

    if (okB) {
        reinterpret_cast<float4*>(out_fg + (size_t)n1 * 4)[0] =
            make_float4(hi[0][0], hi[0][1], hi[0][2], hi[0][3]);
        float4* subB = reinterpret_cast<float4*>(out_sub + (size_t)n1 * 16);
        #pragma unroll
        for (int s = 1; s < S_; s++)
            subB[s - 1] = make_float4(hi[s][0], hi[s][1], hi[s][2], hi[s][3]);
    }
}

extern "C" void kernel_launch(void* const* d_in, const int* in_sizes, int n_in,
                              void* d_out, int out_size) {
    const float* xin  = (const float*)d_in[0];
    const float* cls  = (const float*)d_in[1];
    const float* Wqkv = (const float*)d_in[2];
    const float* bqkv = (const float*)d_in[3];
    const float* Wo   = (const float*)d_in[4];
    const float* bo   = (const float*)d_in[5];
    const float* W1   = (const float*)d_in[6];
    const float* b1   = (const float*)d_in[7];
    const float* W2   = (const float*)d_in[8];
    const float* b2   = (const float*)d_in[9];

    const int N = in_sizes[0] / 16;
    float* out_fg  = (float*)d_out;
    float* out_sub = (float*)d_out + (size_t)N * 4;

    const int grid = (N + 2 * BLK - 1) / (2 * BLK);
    mpt_kernel<<<grid, BLK>>>(xin, cls, Wqkv, bqkv, Wo, bo, W1, b1, W2, b2,
                              out_fg, out_sub, N);
}

// round 3
// speedup vs baseline: 1.3975x; 1.3975x over previous
#include <cuda_runtime.h>
#include <cuda_bf16.h>

// MetaPolicyTransformer: N independent sequences, S=5, D=4, H=2 (hd=2), FF=16, L=3.
// 2 sequences per thread packed into f32x2; per-head restructuring + fused
// out-projection to keep peak live registers under the 255 ceiling (R2 spilled).

#define D_ 4
#define S_ 5
#define FF_ 16
#define L_ 3
#define BLK 128

typedef unsigned long long u64;

__device__ __forceinline__ u64 pk2(float lo, float hi) {
    u64 r; asm("mov.b64 %0, {%1, %2};" : "=l"(r) : "f"(lo), "f"(hi)); return r;
}
__device__ __forceinline__ void upk2(u64 v, float& lo, float& hi) {
    asm("mov.b64 {%0, %1}, %2;" : "=f"(lo), "=f"(hi) : "l"(v));
}
__device__ __forceinline__ u64 fma2(u64 a, u64 b, u64 c) {
    u64 r; asm("fma.rn.f32x2 %0, %1, %2, %3;" : "=l"(r) : "l"(a), "l"(b), "l"(c)); return r;
}
__device__ __forceinline__ u64 add2(u64 a, u64 b) {
    u64 r; asm("add.rn.f32x2 %0, %1, %2;" : "=l"(r) : "l"(a), "l"(b)); return r;
}
__device__ __forceinline__ u64 mul2(u64 a, u64 b) {
    u64 r; asm("mul.rn.f32x2 %0, %1, %2;" : "=l"(r) : "l"(a), "l"(b)); return r;
}
__device__ __forceinline__ float ex2a(float x) {
    float r; asm("ex2.approx.f32 %0, %1;" : "=f"(r) : "f"(x)); return r;
}
__device__ __forceinline__ float rcpa(float x) {
    float r; asm("rcp.approx.f32 %0, %1;" : "=f"(r) : "f"(x)); return r;
}
__device__ __forceinline__ u64 relu2(u64 v) {
    float a, b; upk2(v, a, b);
    return pk2(fmaxf(a, 0.0f), fmaxf(b, 0.0f));
}

__global__ __launch_bounds__(BLK, 2) void mpt_kernel(
    const float* __restrict__ xin,   // (N, 4, 4)
    const float* __restrict__ cls,   // (4,)
    const float* __restrict__ Wqkv,  // (3, 12, 4)
    const float* __restrict__ bqkv,  // (3, 12)
    const float* __restrict__ Wo,    // (3, 4, 4)
    const float* __restrict__ bo,    // (3, 4)
    const float* __restrict__ W1,    // (3, 16, 4)
    const float* __restrict__ b1,    // (3, 16)
    const float* __restrict__ W2,    // (3, 4, 16)
    const float* __restrict__ b2,    // (3, 4)
    float* __restrict__ out_fg,      // (N, 4)
    float* __restrict__ out_sub,     // (N, 16)
    int N)
{
    // all weights pre-packed {w, w} so LDS.64 feeds packed FMA directly
    __shared__ u64 sWqkv[L_ * 48];
    __shared__ u64 sbqkv[L_ * 12];
    __shared__ u64 sWo[L_ * 16];
    __shared__ u64 sbo[L_ * 4];
    __shared__ u64 sW1[L_ * 64];
    __shared__ u64 sb1[L_ * 16];
    __shared__ u64 sW2[L_ * 64];
    __shared__ u64 sb2[L_ * 4];
    __shared__ float scls[4];

    const int t = threadIdx.x;
    for (int i = t; i < L_ * 48; i += BLK) { float w = Wqkv[i]; sWqkv[i] = pk2(w, w); }
    for (int i = t; i < L_ * 12; i += BLK) { float w = bqkv[i]; sbqkv[i] = pk2(w, w); }
    for (int i = t; i < L_ * 16; i += BLK) { float w = Wo[i];   sWo[i]   = pk2(w, w); }
    for (int i = t; i < L_ * 4;  i += BLK) { float w = bo[i];   sbo[i]   = pk2(w, w); }
    for (int i = t; i < L_ * 64; i += BLK) { float w = W1[i];   sW1[i]   = pk2(w, w); }
    for (int i = t; i < L_ * 16; i += BLK) { float w = b1[i];   sb1[i]   = pk2(w, w); }
    for (int i = t; i < L_ * 64; i += BLK) { float w = W2[i];   sW2[i]   = pk2(w, w); }
    for (int i = t; i < L_ * 4;  i += BLK) { float w = b2[i];   sb2[i]   = pk2(w, w); }
    if (t < 4) scls[t] = cls[t];
    __syncthreads();

    const int n0 = blockIdx.x * (2 * BLK) + t;
    const int n1 = n0 + BLK;
    if (n0 >= N) return;
    const bool okB = (n1 < N);
    const int nB = okB ? n1 : n0;

    // PE: pe[s] = [sin(s), cos(s), sin(.01 s), cos(.01 s)]
    const float pe[S_][D_] = {
        { 0.0f,                  1.0f,                  0.0f,                   1.0f                 },
        { 0.84147098480789651f,  0.54030230586813977f,  0.0099998333341666645f, 0.99995000041666528f },
        { 0.90929742682568170f, -0.41614683654714241f,  0.019998666693333084f,  0.99980000666657776f },
        { 0.14112000805986722f, -0.98999249660044542f,  0.029995500337493652f,  0.99955003374899023f },
        { -0.75680249530792820f,-0.65364362086361194f,  0.039989334186634161f,  0.99920010665856564f }
    };

    u64 x[S_][D_];
    #pragma unroll
    for (int d = 0; d < D_; d++) {
        float c = scls[d] + pe[0][d];
        x[0][d] = pk2(c, c);
    }
    const float4* xa = reinterpret_cast<const float4*>(xin + (size_t)n0 * 16);
    const float4* xb = reinterpret_cast<const float4*>(xin + (size_t)nB * 16);
    #pragma unroll
    for (int s = 1; s < S_; s++) {
        float4 ra = xa[s - 1];
        float4 rb = xb[s - 1];
        x[s][0] = pk2(ra.x + pe[s][0], rb.x + pe[s][0]);
        x[s][1] = pk2(ra.y + pe[s][1], rb.y + pe[s][1]);
        x[s][2] = pk2(ra.z + pe[s][2], rb.z + pe[s][2]);
        x[s][3] = pk2(ra.w + pe[s][3], rb.w + pe[s][3]);
    }

    // 1/sqrt(2) * log2(e): softmax in exp2 domain (identical function)
    const float SCL = 0.70710678118654752f * 1.4426950408889634f;
    const u64 SCL2 = pk2(SCL, SCL);

    #pragma unroll 1
    for (int l = 0; l < L_; l++) {
        const u64* wq  = sWqkv + l * 48;
        const u64* bq  = sbqkv + l * 12;
        const u64* wo  = sWo   + l * 16;
        const u64* bov = sbo   + l * 4;
        const u64* w1  = sW1   + l * 64;
        const u64* b1v = sb1   + l * 16;
        const u64* w2  = sW2   + l * 64;
        const u64* b2v = sb2   + l * 4;

        // residual accumulator: nx = x + bo; heads' out-proj accumulates into it
        u64 nx[S_][D_];
        #pragma unroll
        for (int s = 0; s < S_; s++)
            #pragma unroll
            for (int d = 0; d < D_; d++)
                nx[s][d] = add2(x[s][d], bov[d]);

        #pragma unroll
        for (int h = 0; h < 2; h++) {
            // q (pre-scaled), k, v for this head only
            u64 qh[S_][2], kh[S_][2], vh[S_][2];
            #pragma unroll
            for (int s = 0; s < S_; s++) {
                #pragma unroll
                for (int e = 0; e < 2; e++) {
                    const int o = 2 * h + e;
                    u64 aq = bq[o], ak = bq[4 + o], av = bq[8 + o];
                    #pragma unroll
                    for (int c = 0; c < D_; c++) {
                        aq = fma2(x[s][c], wq[o * 4 + c], aq);
                        ak = fma2(x[s][c], wq[(4 + o) * 4 + c], ak);
                        av = fma2(x[s][c], wq[(8 + o) * 4 + c], av);
                    }
                    qh[s][e] = mul2(aq, SCL2);
                    kh[s][e] = ak;
                    vh[s][e] = av;
                }
            }
            #pragma unroll
            for (int i = 0; i < S_; i++) {
                u64 e[S_];
                u64 sum = 0ull;
                #pragma unroll
                for (int j = 0; j < S_; j++) {
                    u64 sc = fma2(qh[i][1], kh[j][1], mul2(qh[i][0], kh[j][0]));
                    float a, b; upk2(sc, a, b);
                    e[j] = pk2(ex2a(a), ex2a(b));
                    sum = add2(sum, e[j]);
                }
                float sa, sb; upk2(sum, sa, sb);
                u64 inv = pk2(rcpa(sa), rcpa(sb));
                u64 o0 = 0ull, o1 = 0ull;
                #pragma unroll
                for (int j = 0; j < S_; j++) {
                    o0 = fma2(e[j], vh[j][0], o0);
                    o1 = fma2(e[j], vh[j][1], o1);
                }
                o0 = mul2(o0, inv);
                o1 = mul2(o1, inv);
                // fused out-projection (columns 2h, 2h+1 of Wo)
                #pragma unroll
                for (int d = 0; d < D_; d++) {
                    nx[i][d] = fma2(o0, wo[d * 4 + 2 * h],     nx[i][d]);
                    nx[i][d] = fma2(o1, wo[d * 4 + 2 * h + 1], nx[i][d]);
                }
            }
        }

        #pragma unroll
        for (int s = 0; s < S_; s++)
            #pragma unroll
            for (int d = 0; d < D_; d++)
                x[s][d] = nx[s][d];

        // FF + residual
        #pragma unroll
        for (int s = 0; s < S_; s++) {
            u64 h1[FF_];
            #pragma unroll
            for (int f = 0; f < FF_; f++) {
                u64 a = b1v[f];
                #pragma unroll
                for (int c = 0; c < D_; c++)
                    a = fma2(x[s][c], w1[f * 4 + c], a);
                h1[f] = relu2(a);
            }
            #pragma unroll
            for (int d = 0; d < D_; d++) {
                u64 a = b2v[d];
                #pragma unroll
                for (int f = 0; f < FF_; f++)
                    a = fma2(h1[f], w2[d * 16 + f], a);
                x[s][d] = add2(x[s][d], a);
            }
        }
    }

    // unpack + store
    {
        float a0, b0, a1, b1f, a2, b2f, a3, b3;
        upk2(x[0][0], a0, b0); upk2(x[0][1], a1, b1f);
        upk2(x[0][2], a2, b2f); upk2(x[0][3], a3, b3);
        reinterpret_cast<float4*>(out_fg + (size_t)n0 * 4)[0] = make_float4(a0, a1, a2, a3);
        if (okB)
            reinterpret_cast<float4*>(out_fg + (size_t)n1 * 4)[0] = make_float4(b0, b1f, b2f, b3);
    }
    float4* subA = reinterpret_cast<float4*>(out_sub + (size_t)n0 * 16);
    float4* subB = reinterpret_cast<float4*>(out_sub + (size_t)n1 * 16);
    #pragma unroll
    for (int s = 1; s < S_; s++) {
        float a0, b0, a1, b1f, a2, b2f, a3, b3;
        upk2(x[s][0], a0, b0); upk2(x[s][1], a1, b1f);
        upk2(x[s][2], a2, b2f); upk2(x[s][3], a3, b3);
        subA[s - 1] = make_float4(a0, a1, a2, a3);
        if (okB) subB[s - 1] = make_float4(b0, b1f, b2f, b3);
    }
}

extern "C" void kernel_launch(void* const* d_in, const int* in_sizes, int n_in,
                              void* d_out, int out_size) {
    const float* xin  = (const float*)d_in[0];
    const float* cls  = (const float*)d_in[1];
    const float* Wqkv = (const float*)d_in[2];
    const float* bqkv = (const float*)d_in[3];
    const float* Wo   = (const float*)d_in[4];
    const float* bo   = (const float*)d_in[5];
    const float* W1   = (const float*)d_in[6];
    const float* b1   = (const float*)d_in[7];
    const float* W2   = (const float*)d_in[8];
    const float* b2   = (const float*)d_in[9];

    const int N = in_sizes[0] / 16;
    float* out_fg  = (float*)d_out;
    float* out_sub = (float*)d_out + (size_t)N * 4;

    const int grid = (N + 2 * BLK - 1) / (2 * BLK);
    mpt_kernel<<<grid, BLK>>>(xin, cls, Wqkv, bqkv, Wo, bo, W1, b1, W2, b2,
                              out_fg, out_sub, N);
}